// round 1
// baseline (speedup 1.0000x reference)
#include <cuda_runtime.h>
#include <cstdint>
#include <cstddef>

// Problem constants (SGCEvaluator): N=100000 nodes, E=1600000 edges, D=128, C=40, 2 hops.
#define N_NODES 100000
#define N_EDGES 1600000
#define D_FEAT  128
#define N_CLASS 40

// Scratch in __device__ globals (no allocations allowed in kernel_launch).
__device__ __align__(256) float g_deg_out[N_NODES];
__device__ __align__(256) float g_deg_in [N_NODES];
__device__ __align__(256) float g_w      [N_EDGES];
__device__ __align__(256) float g_h0     [(size_t)N_NODES * D_FEAT];
__device__ __align__(256) float g_h1     [(size_t)N_NODES * D_FEAT];

// ---------------------------------------------------------------------------
// 1) Weighted degrees: out_deg[src] += w, in_deg[dst] += w
// ---------------------------------------------------------------------------
__global__ void deg_kernel(const int* __restrict__ src,
                           const int* __restrict__ dst,
                           const float* __restrict__ ew,
                           int E)
{
    int e = blockIdx.x * blockDim.x + threadIdx.x;
    if (e < E) {
        float w = ew[e];
        atomicAdd(&g_deg_out[src[e]], w);
        atomicAdd(&g_deg_in [dst[e]], w);
    }
}

// ---------------------------------------------------------------------------
// 2) EdgeWeightNorm('both'): w = ew * rsqrt(out_deg[src]) * rsqrt(in_deg[dst])
// ---------------------------------------------------------------------------
__global__ void norm_kernel(const int* __restrict__ src,
                            const int* __restrict__ dst,
                            const float* __restrict__ ew,
                            int E)
{
    int e = blockIdx.x * blockDim.x + threadIdx.x;
    if (e < E) {
        g_w[e] = ew[e] * rsqrtf(g_deg_out[src[e]]) * rsqrtf(g_deg_in[dst[e]]);
    }
}

// ---------------------------------------------------------------------------
// 3) SpMM hop: hout[dst] += hin[src] * w    (one warp per edge, float4 lanes)
//    Uses vectorized red.global.add.v4.f32 (sm_90+) to quarter the reduction
//    instruction count.
// ---------------------------------------------------------------------------
__global__ void spmm_kernel(const float* __restrict__ hin,
                            float* __restrict__ hout,
                            const int* __restrict__ src,
                            const int* __restrict__ dst,
                            int E)
{
    long long tid = (long long)blockIdx.x * blockDim.x + threadIdx.x;
    int e    = (int)(tid >> 5);
    int lane = (int)(tid & 31);
    if (e >= E) return;

    int s = src[e];          // same address for all 32 lanes -> broadcast
    int d = dst[e];
    float w = g_w[e];

    float4 v = ((const float4*)(hin + (size_t)s * D_FEAT))[lane];
    v.x *= w; v.y *= w; v.z *= w; v.w *= w;

    float* p = hout + (size_t)d * D_FEAT + lane * 4;
    asm volatile("red.global.add.v4.f32 [%0], {%1,%2,%3,%4};"
                 :: "l"(p), "f"(v.x), "f"(v.y), "f"(v.z), "f"(v.w)
                 : "memory");
}

// ---------------------------------------------------------------------------
// 4) FC: out[n,c] = sum_k h[n,k] * W[k,c] + b[c]
//    W (128x40 = 20KB) and 32 h-rows (16KB) staged in shared memory.
// ---------------------------------------------------------------------------
#define NODES_PER_BLOCK 32
#define FC_THREADS 256

__global__ void fc_kernel(const float* __restrict__ h,
                          const float* __restrict__ W,
                          const float* __restrict__ b,
                          float* __restrict__ out,
                          int N)
{
    __shared__ float Ws[D_FEAT * N_CLASS];            // 20480 B
    __shared__ float hs[NODES_PER_BLOCK][D_FEAT];     // 16384 B
    __shared__ float bs[N_CLASS];

    int t = threadIdx.x;
    for (int i = t; i < D_FEAT * N_CLASS; i += FC_THREADS) Ws[i] = W[i];
    if (t < N_CLASS) bs[t] = b[t];

    int n0 = blockIdx.x * NODES_PER_BLOCK;
    for (int i = t; i < NODES_PER_BLOCK * D_FEAT; i += FC_THREADS) {
        int ln = i >> 7;            // i / 128
        int k  = i & 127;
        int n  = n0 + ln;
        hs[ln][k] = (n < N) ? h[(size_t)n * D_FEAT + k] : 0.0f;
    }
    __syncthreads();

    for (int o = t; o < NODES_PER_BLOCK * N_CLASS; o += FC_THREADS) {
        int ln = o / N_CLASS;
        int c  = o % N_CLASS;
        int n  = n0 + ln;
        if (n >= N) continue;

        float acc = bs[c];
        #pragma unroll
        for (int k = 0; k < D_FEAT; k += 4) {
            float4 hv = *(const float4*)&hs[ln][k];
            acc += hv.x * Ws[(k + 0) * N_CLASS + c];
            acc += hv.y * Ws[(k + 1) * N_CLASS + c];
            acc += hv.z * Ws[(k + 2) * N_CLASS + c];
            acc += hv.w * Ws[(k + 3) * N_CLASS + c];
        }
        out[(size_t)n * N_CLASS + c] = acc;
    }
}

// ---------------------------------------------------------------------------
// Launch: degrees -> norm -> hop1 -> hop2 -> fc     (single default stream)
// ---------------------------------------------------------------------------
extern "C" void kernel_launch(void* const* d_in, const int* in_sizes, int n_in,
                              void* d_out, int out_size)
{
    const float* features = (const float*)d_in[0];
    const int*   src      = (const int*)  d_in[1];
    const int*   dst      = (const int*)  d_in[2];
    const float* ew       = (const float*)d_in[3];
    const float* W        = (const float*)d_in[4];
    const float* b        = (const float*)d_in[5];
    float*       out      = (float*)d_out;

    const int E = in_sizes[1];
    const int C = in_sizes[5];
    const int D = in_sizes[4] / C;
    const int N = in_sizes[0] / D;

    void *p_deg_out, *p_deg_in, *p_h0, *p_h1;
    cudaGetSymbolAddress(&p_deg_out, g_deg_out);
    cudaGetSymbolAddress(&p_deg_in,  g_deg_in);
    cudaGetSymbolAddress(&p_h0,      g_h0);
    cudaGetSymbolAddress(&p_h1,      g_h1);

    cudaStream_t s = 0;

    // zero degrees
    cudaMemsetAsync(p_deg_out, 0, (size_t)N * sizeof(float), s);
    cudaMemsetAsync(p_deg_in,  0, (size_t)N * sizeof(float), s);

    // degrees + norm
    {
        int threads = 256;
        int blocks  = (E + threads - 1) / threads;
        deg_kernel <<<blocks, threads, 0, s>>>(src, dst, ew, E);
        norm_kernel<<<blocks, threads, 0, s>>>(src, dst, ew, E);
    }

    // hop 1: features -> g_h0
    cudaMemsetAsync(p_h0, 0, (size_t)N * D_FEAT * sizeof(float), s);
    {
        long long total = (long long)E * 32;
        int threads = 256;
        long long blocks = (total + threads - 1) / threads;
        spmm_kernel<<<(unsigned)blocks, threads, 0, s>>>(
            features, (float*)p_h0, src, dst, E);
    }

    // hop 2: g_h0 -> g_h1
    cudaMemsetAsync(p_h1, 0, (size_t)N * D_FEAT * sizeof(float), s);
    {
        long long total = (long long)E * 32;
        int threads = 256;
        long long blocks = (total + threads - 1) / threads;
        spmm_kernel<<<(unsigned)blocks, threads, 0, s>>>(
            (const float*)p_h0, (float*)p_h1, src, dst, E);
    }

    // fc: g_h1 @ W + b -> out
    {
        int blocks = (N + NODES_PER_BLOCK - 1) / NODES_PER_BLOCK;
        fc_kernel<<<blocks, FC_THREADS, 0, s>>>(
            (const float*)p_h1, W, b, out, N);
    }
}